// round 7
// baseline (speedup 1.0000x reference)
#include <cuda_runtime.h>

// BatchAllTripletLoss fused pipeline — TF32 mma + cp.async + symmetric tiling.
// B=8192, D=256, 512 classes. Upper-triangular tiles only; off-diagonal tiles
// feed both anchors. Labels dtype (int32 vs int64) detected at runtime.

#define DDIM   256
#define BM     128
#define BN     128
#define BK     16
#define MAXPOS 64
#define MAXB   8192
#define SPAD   20      // smem row stride (floats): conflict-free + 16B aligned

__device__ float    g_e[MAXB * DDIM];     // normalized, tf32-rounded embeddings
__device__ int      g_lab[MAXB];
__device__ unsigned g_hn[MAXB];           // hardest-negative distance (float bits)
__device__ float    g_pos[MAXB * MAXPOS];
__device__ int      g_poscnt[MAXB];
__device__ float    g_total;
__device__ int      g_cnt;
__device__ int      g_lab_is64;

// ---------------------------------------------------------------- label dtype detect
// int64 little-endian labels (< 512) have all-zero odd int32 words; int32
// labels make "32 consecutive odd words all zero" impossible (p = 512^-32).
__global__ void k_detect(const int* lab32) {
    int t = threadIdx.x;                 // 0..31
    int v = lab32[2 * t + 1];
    unsigned b = __ballot_sync(0xffffffffu, v == 0);
    if (t == 0) g_lab_is64 = (b == 0xffffffffu) ? 1 : 0;
}

// ---------------------------------------------------------------- init
__global__ void k_init(int B) {
    int i = blockIdx.x * blockDim.x + threadIdx.x;
    if (i < B) {
        g_hn[i]     = __float_as_uint(1e9f);
        g_poscnt[i] = 0;
    }
    if (i == 0) { g_total = 0.f; g_cnt = 0; }
}

// ---------------------------------------------------------------- normalize (+ tf32 round)
__device__ __forceinline__ float tf32r(float x) {
    unsigned u;
    asm("cvt.rna.tf32.f32 %0, %1;" : "=r"(u) : "f"(x));
    return __uint_as_float(u);
}

__global__ void k_normalize(const float* __restrict__ x,
                            const void* __restrict__ lab, int B) {
    int row = blockIdx.x;
    int t   = threadIdx.x;  // 0..63
    float4 v = ((const float4*)(x + (size_t)row * DDIM))[t];
    float s = v.x*v.x + v.y*v.y + v.z*v.z + v.w*v.w;
    #pragma unroll
    for (int o = 16; o > 0; o >>= 1) s += __shfl_down_sync(0xffffffffu, s, o);
    __shared__ float ws[2];
    if ((t & 31) == 0) ws[t >> 5] = s;
    __syncthreads();
    float rn = 1.f / fmaxf(sqrtf(ws[0] + ws[1]), 1e-12f);
    v.x = tf32r(v.x * rn); v.y = tf32r(v.y * rn);
    v.z = tf32r(v.z * rn); v.w = tf32r(v.w * rn);
    ((float4*)(g_e + (size_t)row * DDIM))[t] = v;
    if (t == 0) {
        g_lab[row] = g_lab_is64 ? (int)((const long long*)lab)[row]
                                : ((const int*)lab)[row];
    }
}

// ---------------------------------------------------------------- async copy helpers
__device__ __forceinline__ unsigned smem_u32(const void* p) {
    return (unsigned)__cvta_generic_to_shared(p);
}
__device__ __forceinline__ void cp16(unsigned dst, const void* src) {
    asm volatile("cp.async.cg.shared.global [%0], [%1], 16;\n" :: "r"(dst), "l"(src));
}
__device__ __forceinline__ void cp_commit() {
    asm volatile("cp.async.commit_group;\n" ::: "memory");
}
__device__ __forceinline__ void cp_wait0() {
    asm volatile("cp.async.wait_group 0;\n" ::: "memory");
}

// ---------------------------------------------------------------- tf32 mma
__device__ __forceinline__ void mma_tf32(float c[4],
                                         unsigned a0, unsigned a1, unsigned a2, unsigned a3,
                                         unsigned b0, unsigned b1) {
    asm volatile(
        "mma.sync.aligned.m16n8k8.row.col.f32.tf32.tf32.f32 "
        "{%0,%1,%2,%3}, {%4,%5,%6,%7}, {%8,%9}, {%0,%1,%2,%3};"
        : "+f"(c[0]), "+f"(c[1]), "+f"(c[2]), "+f"(c[3])
        : "r"(a0), "r"(a1), "r"(a2), "r"(a3), "r"(b0), "r"(b1));
}

// ---------------------------------------------------------------- fused GEMM
__global__ void __launch_bounds__(256, 2) k_gemm() {
    const int bi = blockIdx.y, bj = blockIdx.x;
    if (bj < bi) return;                  // symmetric: skip lower triangle
    const bool offd = (bj != bi);

    __shared__ float As[2][BM][SPAD];
    __shared__ float Bs[2][BN][SPAD];
    __shared__ int   Li[BM], Lj[BN];
    __shared__ unsigned sMin[BM];         // per-row (anchor i) min
    __shared__ unsigned sMinC[BN];        // per-col (anchor j) min

    const int tid  = threadIdx.x;
    const int lane = tid & 31;
    const int wid  = tid >> 5;
    const int warpM = wid >> 2;          // 0..1
    const int warpN = wid & 3;           // 0..3
    const int grp  = lane >> 2;          // 0..7
    const int thr  = lane & 3;           // 0..3

    const int aBase = bi * BM;
    const int jBase = bj * BN;

    if (tid < BM) {
        Li[tid]   = g_lab[aBase + tid];
        sMin[tid] = __float_as_uint(1e9f);
    } else {
        Lj[tid - BM]    = g_lab[jBase + tid - BM];
        sMinC[tid - BM] = __float_as_uint(1e9f);
    }

    const int r0 = tid >> 2;
    const int kk = (tid & 3) << 2;
    const float* gA0 = g_e + (size_t)(aBase + r0)      * DDIM + kk;
    const float* gA1 = g_e + (size_t)(aBase + r0 + 64) * DDIM + kk;
    const float* gB0 = g_e + (size_t)(jBase + r0)      * DDIM + kk;
    const float* gB1 = g_e + (size_t)(jBase + r0 + 64) * DDIM + kk;
    unsigned sA0[2], sA1[2], sB0[2], sB1[2];
    #pragma unroll
    for (int b = 0; b < 2; ++b) {
        sA0[b] = smem_u32(&As[b][r0][kk]);
        sA1[b] = smem_u32(&As[b][r0 + 64][kk]);
        sB0[b] = smem_u32(&Bs[b][r0][kk]);
        sB1[b] = smem_u32(&Bs[b][r0 + 64][kk]);
    }

    cp16(sA0[0], gA0); cp16(sA1[0], gA1);
    cp16(sB0[0], gB0); cp16(sB1[0], gB1);
    cp_commit();
    cp_wait0();
    __syncthreads();

    float acc[4][4][4];
    #pragma unroll
    for (int mf = 0; mf < 4; ++mf)
        #pragma unroll
        for (int nf = 0; nf < 4; ++nf)
            #pragma unroll
            for (int e = 0; e < 4; ++e) acc[mf][nf][e] = 0.f;

    for (int kt = 0; kt < DDIM / BK; ++kt) {
        const int buf = kt & 1;
        const bool pre = (kt + 1) < (DDIM / BK);
        if (pre) {
            const int nb  = buf ^ 1;
            const int off = (kt + 1) * BK;
            cp16(sA0[nb], gA0 + off); cp16(sA1[nb], gA1 + off);
            cp16(sB0[nb], gB0 + off); cp16(sB1[nb], gB1 + off);
            cp_commit();
        }

        #pragma unroll
        for (int ks = 0; ks < 2; ++ks) {
            const int k0 = ks * 8;
            unsigned bfr[4][2];
            #pragma unroll
            for (int nf = 0; nf < 4; ++nf) {
                int col = warpN * 32 + nf * 8 + grp;
                bfr[nf][0] = __float_as_uint(Bs[buf][col][k0 + thr]);
                bfr[nf][1] = __float_as_uint(Bs[buf][col][k0 + 4 + thr]);
            }
            #pragma unroll
            for (int mf = 0; mf < 4; ++mf) {
                int row = warpM * 64 + mf * 16 + grp;
                unsigned a0 = __float_as_uint(As[buf][row][k0 + thr]);
                unsigned a1 = __float_as_uint(As[buf][row + 8][k0 + thr]);
                unsigned a2 = __float_as_uint(As[buf][row][k0 + 4 + thr]);
                unsigned a3 = __float_as_uint(As[buf][row + 8][k0 + 4 + thr]);
                #pragma unroll
                for (int nf = 0; nf < 4; ++nf)
                    mma_tf32(acc[mf][nf], a0, a1, a2, a3, bfr[nf][0], bfr[nf][1]);
            }
        }

        if (pre) cp_wait0();
        __syncthreads();
    }

    // epilogue: distances; row-side always, col-side (mirror) when off-diagonal
    float colMn[4][2];
    #pragma unroll
    for (int nf = 0; nf < 4; ++nf) { colMn[nf][0] = 1e9f; colMn[nf][1] = 1e9f; }

    #pragma unroll
    for (int mf = 0; mf < 4; ++mf) {
        #pragma unroll
        for (int h = 0; h < 2; ++h) {
            const int row = warpM * 64 + mf * 16 + grp + h * 8;
            const int gi  = aBase + row;
            const int li  = Li[row];
            float mn = 1e9f;
            #pragma unroll
            for (int nf = 0; nf < 4; ++nf) {
                #pragma unroll
                for (int e = 0; e < 2; ++e) {
                    float c   = acc[mf][nf][h * 2 + e];
                    int   col = warpN * 32 + nf * 8 + 2 * thr + e;
                    int   gj  = jBase + col;
                    float d   = fmaxf(1.0f - c, 0.0f);
                    int   lj  = Lj[col];
                    if (li != lj) {
                        mn = fminf(mn, d);
                        if (offd) colMn[nf][e] = fminf(colMn[nf][e], d);
                    } else if (gi != gj) {
                        int idx = atomicAdd(&g_poscnt[gi], 1);
                        if (idx < MAXPOS) g_pos[gi * MAXPOS + idx] = d;
                        if (offd) {      // mirror pair (gj, gi)
                            int idx2 = atomicAdd(&g_poscnt[gj], 1);
                            if (idx2 < MAXPOS) g_pos[gj * MAXPOS + idx2] = d;
                        }
                    }
                }
            }
            atomicMin(&sMin[row], __float_as_uint(mn));
        }
    }
    if (offd) {
        #pragma unroll
        for (int nf = 0; nf < 4; ++nf)
            #pragma unroll
            for (int e = 0; e < 2; ++e) {
                int col = warpN * 32 + nf * 8 + 2 * thr + e;
                atomicMin(&sMinC[col], __float_as_uint(colMn[nf][e]));
            }
    }
    __syncthreads();
    if (tid < BM) {
        atomicMin(&g_hn[aBase + tid], sMin[tid]);
    } else if (offd) {
        atomicMin(&g_hn[jBase + tid - BM], sMinC[tid - BM]);
    }
}

// ---------------------------------------------------------------- reduction
__global__ void k_reduce(int B) {
    int i = blockIdx.x * blockDim.x + threadIdx.x;
    float s = 0.f; int c = 0;
    if (i < B) {
        float hn = __uint_as_float(g_hn[i]);
        int   n  = min(g_poscnt[i], MAXPOS);
        for (int e = 0; e < n; ++e) {
            float l = g_pos[i * MAXPOS + e] - hn + 1.0f;   // MARGIN = 1
            if (l > 0.f) { s += l; c++; }
        }
    }
    __shared__ float ss[256];
    __shared__ int   sc[256];
    int t = threadIdx.x;
    ss[t] = s; sc[t] = c;
    __syncthreads();
    for (int o = 128; o > 0; o >>= 1) {
        if (t < o) { ss[t] += ss[t + o]; sc[t] += sc[t + o]; }
        __syncthreads();
    }
    if (t == 0) {
        atomicAdd(&g_total, ss[0]);
        atomicAdd(&g_cnt,   sc[0]);
    }
}

__global__ void k_final(float* out) {
    int   c = g_cnt;
    out[0] = (c > 0) ? g_total / (float)c : 0.0f;
}

// ---------------------------------------------------------------- launch
extern "C" void kernel_launch(void* const* d_in, const int* in_sizes, int n_in,
                              void* d_out, int out_size) {
    const float* emb = (const float*)d_in[0];
    const void*  lab = d_in[1];
    float*       out = (float*)d_out;
    int B = in_sizes[1];   // 8192

    k_detect<<<1, 32>>>((const int*)lab);
    k_init<<<(B + 255) / 256, 256>>>(B);
    k_normalize<<<B, 64>>>(emb, lab, B);
    dim3 grid(B / BN, B / BM);
    k_gemm<<<grid, 256>>>();
    k_reduce<<<(B + 255) / 256, 256>>>(B);
    k_final<<<1, 1>>>(out);
}

// round 14
// speedup vs baseline: 1.1175x; 1.1175x over previous
#include <cuda_runtime.h>

// BatchAllTripletLoss fused pipeline — TF32 mma + cp.async + symmetric tiling.
// R8-R13: k-permuted layout (LDS.64 fragment loads, SPAD=24) + flattened
// triangular grid (2080 CTAs, no early-exit waste).

#define DDIM   256
#define BM     128
#define BN     128
#define BK     16
#define MAXPOS 64
#define MAXB   8192
#define SPAD   24      // smem row stride (floats): LDS.64 conflict-free
#define NTILE  64      // B / BM
#define NTRI   2080    // NTILE*(NTILE+1)/2

__device__ float    g_e[MAXB * DDIM];     // normalized, tf32, k-permuted
__device__ int      g_lab[MAXB];
__device__ unsigned g_hn[MAXB];           // hardest-negative distance (float bits)
__device__ float    g_pos[MAXB * MAXPOS];
__device__ int      g_poscnt[MAXB];
__device__ float    g_total;
__device__ int      g_cnt;
__device__ int      g_lab_is64;

// ---------------------------------------------------------------- label dtype detect
__global__ void k_detect(const int* lab32) {
    int t = threadIdx.x;                 // 0..31
    int v = lab32[2 * t + 1];
    unsigned b = __ballot_sync(0xffffffffu, v == 0);
    if (t == 0) g_lab_is64 = (b == 0xffffffffu) ? 1 : 0;
}

// ---------------------------------------------------------------- init
__global__ void k_init(int B) {
    int i = blockIdx.x * blockDim.x + threadIdx.x;
    if (i < B) {
        g_hn[i]     = __float_as_uint(1e9f);
        g_poscnt[i] = 0;
    }
    if (i == 0) { g_total = 0.f; g_cnt = 0; }
}

// ---------------------------------------------------------------- normalize (+ tf32 + permute)
__device__ __forceinline__ float tf32r(float x) {
    unsigned u;
    asm("cvt.rna.tf32.f32 %0, %1;" : "=r"(u) : "f"(x));
    return __uint_as_float(u);
}

// k-permutation: each 8-group stored as [0,4,1,5,2,6,3,7] so fragment pairs
// (k, k+4) are adjacent words -> LDS.64 in the GEMM.
__global__ void k_normalize(const float* __restrict__ x,
                            const void* __restrict__ lab, int B) {
    int row = blockIdx.x;
    int t   = threadIdx.x;  // 0..63, handles logical k = 4t..4t+3
    float4 v = ((const float4*)(x + (size_t)row * DDIM))[t];
    float s = v.x*v.x + v.y*v.y + v.z*v.z + v.w*v.w;
    #pragma unroll
    for (int o = 16; o > 0; o >>= 1) s += __shfl_down_sync(0xffffffffu, s, o);
    __shared__ float ws[2];
    if ((t & 31) == 0) ws[t >> 5] = s;
    __syncthreads();
    float rn = 1.f / fmaxf(sqrtf(ws[0] + ws[1]), 1e-12f);
    float* dst = g_e + (size_t)row * DDIM + (t >> 1) * 8 + (t & 1);
    dst[0] = tf32r(v.x * rn);
    dst[2] = tf32r(v.y * rn);
    dst[4] = tf32r(v.z * rn);
    dst[6] = tf32r(v.w * rn);
    if (t == 0) {
        g_lab[row] = g_lab_is64 ? (int)((const long long*)lab)[row]
                                : ((const int*)lab)[row];
    }
}

// ---------------------------------------------------------------- async copy helpers
__device__ __forceinline__ unsigned smem_u32(const void* p) {
    return (unsigned)__cvta_generic_to_shared(p);
}
__device__ __forceinline__ void cp16(unsigned dst, const void* src) {
    asm volatile("cp.async.cg.shared.global [%0], [%1], 16;\n" :: "r"(dst), "l"(src));
}
__device__ __forceinline__ void cp_commit() {
    asm volatile("cp.async.commit_group;\n" ::: "memory");
}
__device__ __forceinline__ void cp_wait0() {
    asm volatile("cp.async.wait_group 0;\n" ::: "memory");
}

// ---------------------------------------------------------------- tf32 mma
__device__ __forceinline__ void mma_tf32(float c[4],
                                         unsigned a0, unsigned a1, unsigned a2, unsigned a3,
                                         unsigned b0, unsigned b1) {
    asm volatile(
        "mma.sync.aligned.m16n8k8.row.col.f32.tf32.tf32.f32 "
        "{%0,%1,%2,%3}, {%4,%5,%6,%7}, {%8,%9}, {%0,%1,%2,%3};"
        : "+f"(c[0]), "+f"(c[1]), "+f"(c[2]), "+f"(c[3])
        : "r"(a0), "r"(a1), "r"(a2), "r"(a3), "r"(b0), "r"(b1));
}

// ---------------------------------------------------------------- fused GEMM
// Flattened upper-triangular grid: blockIdx.x in [0, 2080).
// Row bi has (64-bi) tiles; S(r) = 64r - r(r-1)/2 tiles precede row r.
__global__ void __launch_bounds__(256, 2) k_gemm() {
    int id = blockIdx.x;
    int bi = (int)((129.0f - sqrtf(16641.0f - 8.0f * (float)id)) * 0.5f);
    while (64 * bi - bi * (bi - 1) / 2 > id) --bi;
    while (64 * (bi + 1) - (bi + 1) * bi / 2 <= id) ++bi;
    const int bj = bi + (id - (64 * bi - bi * (bi - 1) / 2));
    const bool offd = (bj != bi);

    __shared__ float As[2][BM][SPAD];
    __shared__ float Bs[2][BN][SPAD];
    __shared__ int   Li[BM], Lj[BN];
    __shared__ unsigned sMin[BM];         // per-row (anchor i) min
    __shared__ unsigned sMinC[BN];        // per-col (anchor j) min

    const int tid  = threadIdx.x;
    const int lane = tid & 31;
    const int wid  = tid >> 5;
    const int warpM = wid >> 2;          // 0..1
    const int warpN = wid & 3;           // 0..3
    const int grp  = lane >> 2;          // 0..7
    const int thr  = lane & 3;           // 0..3

    const int aBase = bi * BM;
    const int jBase = bj * BN;

    if (tid < BM) {
        Li[tid]   = g_lab[aBase + tid];
        sMin[tid] = __float_as_uint(1e9f);
    } else {
        Lj[tid - BM]    = g_lab[jBase + tid - BM];
        sMinC[tid - BM] = __float_as_uint(1e9f);
    }

    const int r0 = tid >> 2;
    const int kk = (tid & 3) << 2;
    const float* gA0 = g_e + (size_t)(aBase + r0)      * DDIM + kk;
    const float* gA1 = g_e + (size_t)(aBase + r0 + 64) * DDIM + kk;
    const float* gB0 = g_e + (size_t)(jBase + r0)      * DDIM + kk;
    const float* gB1 = g_e + (size_t)(jBase + r0 + 64) * DDIM + kk;
    unsigned sA0[2], sA1[2], sB0[2], sB1[2];
    #pragma unroll
    for (int b = 0; b < 2; ++b) {
        sA0[b] = smem_u32(&As[b][r0][kk]);
        sA1[b] = smem_u32(&As[b][r0 + 64][kk]);
        sB0[b] = smem_u32(&Bs[b][r0][kk]);
        sB1[b] = smem_u32(&Bs[b][r0 + 64][kk]);
    }

    cp16(sA0[0], gA0); cp16(sA1[0], gA1);
    cp16(sB0[0], gB0); cp16(sB1[0], gB1);
    cp_commit();
    cp_wait0();
    __syncthreads();

    float acc[4][4][4];
    #pragma unroll
    for (int mf = 0; mf < 4; ++mf)
        #pragma unroll
        for (int nf = 0; nf < 4; ++nf)
            #pragma unroll
            for (int e = 0; e < 4; ++e) acc[mf][nf][e] = 0.f;

    for (int kt = 0; kt < DDIM / BK; ++kt) {
        const int buf = kt & 1;
        const bool pre = (kt + 1) < (DDIM / BK);
        if (pre) {
            const int nb  = buf ^ 1;
            const int off = (kt + 1) * BK;
            cp16(sA0[nb], gA0 + off); cp16(sA1[nb], gA1 + off);
            cp16(sB0[nb], gB0 + off); cp16(sB1[nb], gB1 + off);
            cp_commit();
        }

        #pragma unroll
        for (int ks = 0; ks < 2; ++ks) {
            const int k0 = ks * 8;           // permuted: pair (k,k+4) at k0+2thr
            unsigned bfr[4][2];
            #pragma unroll
            for (int nf = 0; nf < 4; ++nf) {
                int col = warpN * 32 + nf * 8 + grp;
                float2 b01 = *(const float2*)&Bs[buf][col][k0 + 2 * thr];
                bfr[nf][0] = __float_as_uint(b01.x);   // k0+thr
                bfr[nf][1] = __float_as_uint(b01.y);   // k0+4+thr
            }
            #pragma unroll
            for (int mf = 0; mf < 4; ++mf) {
                int row = warpM * 64 + mf * 16 + grp;
                float2 aA = *(const float2*)&As[buf][row][k0 + 2 * thr];      // a0,a2
                float2 aB = *(const float2*)&As[buf][row + 8][k0 + 2 * thr];  // a1,a3
                unsigned a0 = __float_as_uint(aA.x);
                unsigned a1 = __float_as_uint(aB.x);
                unsigned a2 = __float_as_uint(aA.y);
                unsigned a3 = __float_as_uint(aB.y);
                #pragma unroll
                for (int nf = 0; nf < 4; ++nf)
                    mma_tf32(acc[mf][nf], a0, a1, a2, a3, bfr[nf][0], bfr[nf][1]);
            }
        }

        if (pre) cp_wait0();
        __syncthreads();
    }

    // epilogue: distances; row-side always, col-side (mirror) when off-diagonal
    float colMn[4][2];
    #pragma unroll
    for (int nf = 0; nf < 4; ++nf) { colMn[nf][0] = 1e9f; colMn[nf][1] = 1e9f; }

    #pragma unroll
    for (int mf = 0; mf < 4; ++mf) {
        #pragma unroll
        for (int h = 0; h < 2; ++h) {
            const int row = warpM * 64 + mf * 16 + grp + h * 8;
            const int gi  = aBase + row;
            const int li  = Li[row];
            float mn = 1e9f;
            #pragma unroll
            for (int nf = 0; nf < 4; ++nf) {
                #pragma unroll
                for (int e = 0; e < 2; ++e) {
                    float c   = acc[mf][nf][h * 2 + e];
                    int   col = warpN * 32 + nf * 8 + 2 * thr + e;
                    int   gj  = jBase + col;
                    float d   = fmaxf(1.0f - c, 0.0f);
                    int   lj  = Lj[col];
                    if (li != lj) {
                        mn = fminf(mn, d);
                        if (offd) colMn[nf][e] = fminf(colMn[nf][e], d);
                    } else if (gi != gj) {
                        int idx = atomicAdd(&g_poscnt[gi], 1);
                        if (idx < MAXPOS) g_pos[gi * MAXPOS + idx] = d;
                        if (offd) {      // mirror pair (gj, gi)
                            int idx2 = atomicAdd(&g_poscnt[gj], 1);
                            if (idx2 < MAXPOS) g_pos[gj * MAXPOS + idx2] = d;
                        }
                    }
                }
            }
            atomicMin(&sMin[row], __float_as_uint(mn));
        }
    }
    if (offd) {
        #pragma unroll
        for (int nf = 0; nf < 4; ++nf)
            #pragma unroll
            for (int e = 0; e < 2; ++e) {
                int col = warpN * 32 + nf * 8 + 2 * thr + e;
                atomicMin(&sMinC[col], __float_as_uint(colMn[nf][e]));
            }
    }
    __syncthreads();
    if (tid < BM) {
        atomicMin(&g_hn[aBase + tid], sMin[tid]);
    } else if (offd) {
        atomicMin(&g_hn[jBase + tid - BM], sMinC[tid - BM]);
    }
}

// ---------------------------------------------------------------- reduction
__global__ void k_reduce(int B) {
    int i = blockIdx.x * blockDim.x + threadIdx.x;
    float s = 0.f; int c = 0;
    if (i < B) {
        float hn = __uint_as_float(g_hn[i]);
        int   n  = min(g_poscnt[i], MAXPOS);
        for (int e = 0; e < n; ++e) {
            float l = g_pos[i * MAXPOS + e] - hn + 1.0f;   // MARGIN = 1
            if (l > 0.f) { s += l; c++; }
        }
    }
    __shared__ float ss[256];
    __shared__ int   sc[256];
    int t = threadIdx.x;
    ss[t] = s; sc[t] = c;
    __syncthreads();
    for (int o = 128; o > 0; o >>= 1) {
        if (t < o) { ss[t] += ss[t + o]; sc[t] += sc[t + o]; }
        __syncthreads();
    }
    if (t == 0) {
        atomicAdd(&g_total, ss[0]);
        atomicAdd(&g_cnt,   sc[0]);
    }
}

__global__ void k_final(float* out) {
    int   c = g_cnt;
    out[0] = (c > 0) ? g_total / (float)c : 0.0f;
}

// ---------------------------------------------------------------- launch
extern "C" void kernel_launch(void* const* d_in, const int* in_sizes, int n_in,
                              void* d_out, int out_size) {
    const float* emb = (const float*)d_in[0];
    const void*  lab = d_in[1];
    float*       out = (float*)d_out;
    int B = in_sizes[1];   // 8192

    k_detect<<<1, 32>>>((const int*)lab);
    k_init<<<(B + 255) / 256, 256>>>(B);
    k_normalize<<<B, 64>>>(emb, lab, B);
    k_gemm<<<NTRI, 256>>>();
    k_reduce<<<(B + 255) / 256, 256>>>(B);
    k_final<<<1, 1>>>(out);
}

// round 16
// speedup vs baseline: 1.4872x; 1.3308x over previous
#include <cuda_runtime.h>
#include <cuda_bf16.h>

// BatchAllTripletLoss fused pipeline — BF16 m16n8k16 mma + cp.async +
// symmetric triangular tiling. R14/R15: tf32 -> bf16 (halves MMA count,
// smem bytes, LDS instructions); zero-pad conflict-free 32B rows.

#define DDIM   256
#define BM     128
#define BN     128
#define BK     16      // k per tile == k per mma
#define MAXPOS 64
#define MAXB   8192
#define NTILE  64      // B / BM
#define NTRI   2080    // NTILE*(NTILE+1)/2

__device__ __nv_bfloat16 g_e[MAXB * DDIM]; // normalized, bf16, k-permuted
__device__ int      g_lab[MAXB];
__device__ unsigned g_hn[MAXB];            // hardest-negative distance (float bits)
__device__ float    g_pos[MAXB * MAXPOS];
__device__ int      g_poscnt[MAXB];
__device__ float    g_total;
__device__ int      g_cnt;
__device__ int      g_lab_is64;

// ---------------------------------------------------------------- label dtype detect
__global__ void k_detect(const int* lab32) {
    int t = threadIdx.x;                 // 0..31
    int v = lab32[2 * t + 1];
    unsigned b = __ballot_sync(0xffffffffu, v == 0);
    if (t == 0) g_lab_is64 = (b == 0xffffffffu) ? 1 : 0;
}

// ---------------------------------------------------------------- init
__global__ void k_init(int B) {
    int i = blockIdx.x * blockDim.x + threadIdx.x;
    if (i < B) {
        g_hn[i]     = __float_as_uint(1e9f);
        g_poscnt[i] = 0;
    }
    if (i == 0) { g_total = 0.f; g_cnt = 0; }
}

// ---------------------------------------------------------------- normalize (+ bf16 + permute)
// Per 16-k group, layout [0,1,8,9,2,3,10,11,4,5,12,13,6,7,14,15]:
// fragment pairs (2t,2t+1) and (2t+8,2t+9) sit at element offset 4t..4t+3.
__global__ void k_normalize(const float* __restrict__ x,
                            const void* __restrict__ lab, int B) {
    int row = blockIdx.x;
    int t   = threadIdx.x;  // 0..63, logical k = 4t..4t+3
    float4 v = ((const float4*)(x + (size_t)row * DDIM))[t];
    float s = v.x*v.x + v.y*v.y + v.z*v.z + v.w*v.w;
    #pragma unroll
    for (int o = 16; o > 0; o >>= 1) s += __shfl_down_sync(0xffffffffu, s, o);
    __shared__ float ws[2];
    if ((t & 31) == 0) ws[t >> 5] = s;
    __syncthreads();
    float rn = 1.f / fmaxf(sqrtf(ws[0] + ws[1]), 1e-12f);

    __nv_bfloat162 lo, hi;
    lo.x = __float2bfloat16(v.x * rn); lo.y = __float2bfloat16(v.y * rn);
    hi.x = __float2bfloat16(v.z * rn); hi.y = __float2bfloat16(v.w * rn);

    int g = t >> 2, u = t & 3;
    __nv_bfloat162* base2 = (__nv_bfloat162*)(g_e + (size_t)row * DDIM + g * 16);
    int iLo, iHi;           // bf16x2 slot indices within the 16-elem group
    if (u < 2) { iLo = 4 * u;            iHi = 4 * u + 2; }        // k<8 half
    else       { iLo = 4 * (u - 2) + 1;  iHi = 4 * (u - 2) + 3; }  // k>=8 half
    base2[iLo] = lo;
    base2[iHi] = hi;

    if (t == 0) {
        g_lab[row] = g_lab_is64 ? (int)((const long long*)lab)[row]
                                : ((const int*)lab)[row];
    }
}

// ---------------------------------------------------------------- async copy helpers
__device__ __forceinline__ unsigned smem_u32(const void* p) {
    return (unsigned)__cvta_generic_to_shared(p);
}
__device__ __forceinline__ void cp16(unsigned dst, const void* src) {
    asm volatile("cp.async.cg.shared.global [%0], [%1], 16;\n" :: "r"(dst), "l"(src));
}
__device__ __forceinline__ void cp_commit() {
    asm volatile("cp.async.commit_group;\n" ::: "memory");
}
__device__ __forceinline__ void cp_wait0() {
    asm volatile("cp.async.wait_group 0;\n" ::: "memory");
}

// ---------------------------------------------------------------- bf16 mma (m16n8k16)
__device__ __forceinline__ void mma_bf16(float c[4],
                                         unsigned a0, unsigned a1, unsigned a2, unsigned a3,
                                         unsigned b0, unsigned b1) {
    asm volatile(
        "mma.sync.aligned.m16n8k16.row.col.f32.bf16.bf16.f32 "
        "{%0,%1,%2,%3}, {%4,%5,%6,%7}, {%8,%9}, {%0,%1,%2,%3};"
        : "+f"(c[0]), "+f"(c[1]), "+f"(c[2]), "+f"(c[3])
        : "r"(a0), "r"(a1), "r"(a2), "r"(a3), "r"(b0), "r"(b1));
}

// ---------------------------------------------------------------- fused GEMM
// Flattened upper-triangular grid: blockIdx.x in [0, 2080).
__global__ void __launch_bounds__(256, 2) k_gemm() {
    int id = blockIdx.x;
    int bi = (int)((129.0f - sqrtf(16641.0f - 8.0f * (float)id)) * 0.5f);
    while (64 * bi - bi * (bi - 1) / 2 > id) --bi;
    while (64 * (bi + 1) - (bi + 1) * bi / 2 <= id) ++bi;
    const int bj = bi + (id - (64 * bi - bi * (bi - 1) / 2));
    const bool offd = (bj != bi);

    __shared__ __nv_bfloat16 As[2][BM][BK];   // 32B rows: bank-conflict-free
    __shared__ __nv_bfloat16 Bs[2][BN][BK];
    __shared__ int   Li[BM], Lj[BN];
    __shared__ unsigned sMin[BM];         // per-row (anchor i) min
    __shared__ unsigned sMinC[BN];        // per-col (anchor j) min

    const int tid  = threadIdx.x;
    const int lane = tid & 31;
    const int wid  = tid >> 5;
    const int warpM = wid >> 2;          // 0..1
    const int warpN = wid & 3;           // 0..3
    const int grp  = lane >> 2;          // 0..7
    const int thr  = lane & 3;           // 0..3

    const int aBase = bi * BM;
    const int jBase = bj * BN;

    if (tid < BM) {
        Li[tid]   = g_lab[aBase + tid];
        sMin[tid] = __float_as_uint(1e9f);
    } else {
        Lj[tid - BM]    = g_lab[jBase + tid - BM];
        sMinC[tid - BM] = __float_as_uint(1e9f);
    }

    // staging: thread covers one 16B chunk of A and one of B per tile
    const int r0 = tid >> 1;              // 0..127
    const int hf = (tid & 1) * 8;         // element offset 0 or 8
    const __nv_bfloat16* gA = g_e + (size_t)(aBase + r0) * DDIM + hf;
    const __nv_bfloat16* gB = g_e + (size_t)(jBase + r0) * DDIM + hf;
    unsigned sA[2], sB[2];
    #pragma unroll
    for (int b = 0; b < 2; ++b) {
        sA[b] = smem_u32(&As[b][r0][hf]);
        sB[b] = smem_u32(&Bs[b][r0][hf]);
    }

    cp16(sA[0], gA); cp16(sB[0], gB);
    cp_commit();
    cp_wait0();
    __syncthreads();

    float acc[4][4][4];
    #pragma unroll
    for (int mf = 0; mf < 4; ++mf)
        #pragma unroll
        for (int nf = 0; nf < 4; ++nf)
            #pragma unroll
            for (int e = 0; e < 4; ++e) acc[mf][nf][e] = 0.f;

    for (int kt = 0; kt < DDIM / BK; ++kt) {
        const int buf = kt & 1;
        const bool pre = (kt + 1) < (DDIM / BK);
        if (pre) {
            const int nb  = buf ^ 1;
            const int off = (kt + 1) * BK;
            cp16(sA[nb], gA + off);
            cp16(sB[nb], gB + off);
            cp_commit();
        }

        // one m16n8k16 k-step per tile; permuted layout: pairs at [4*thr]
        unsigned bfr[4][2];
        #pragma unroll
        for (int nf = 0; nf < 4; ++nf) {
            int col = warpN * 32 + nf * 8 + grp;
            uint2 b01 = *(const uint2*)&Bs[buf][col][4 * thr];
            bfr[nf][0] = b01.x;    // k = 2t, 2t+1
            bfr[nf][1] = b01.y;    // k = 2t+8, 2t+9
        }
        #pragma unroll
        for (int mf = 0; mf < 4; ++mf) {
            int row = warpM * 64 + mf * 16 + grp;
            uint2 aL = *(const uint2*)&As[buf][row][4 * thr];      // a0, a2
            uint2 aH = *(const uint2*)&As[buf][row + 8][4 * thr];  // a1, a3
            #pragma unroll
            for (int nf = 0; nf < 4; ++nf)
                mma_bf16(acc[mf][nf], aL.x, aH.x, aL.y, aH.y,
                         bfr[nf][0], bfr[nf][1]);
        }

        if (pre) cp_wait0();
        __syncthreads();
    }

    // epilogue: distances; row-side always, col-side (mirror) when off-diagonal
    float colMn[4][2];
    #pragma unroll
    for (int nf = 0; nf < 4; ++nf) { colMn[nf][0] = 1e9f; colMn[nf][1] = 1e9f; }

    #pragma unroll
    for (int mf = 0; mf < 4; ++mf) {
        #pragma unroll
        for (int h = 0; h < 2; ++h) {
            const int row = warpM * 64 + mf * 16 + grp + h * 8;
            const int gi  = aBase + row;
            const int li  = Li[row];
            float mn = 1e9f;
            #pragma unroll
            for (int nf = 0; nf < 4; ++nf) {
                #pragma unroll
                for (int e = 0; e < 2; ++e) {
                    float c   = acc[mf][nf][h * 2 + e];
                    int   col = warpN * 32 + nf * 8 + 2 * thr + e;
                    int   gj  = jBase + col;
                    float d   = fmaxf(1.0f - c, 0.0f);
                    int   lj  = Lj[col];
                    if (li != lj) {
                        mn = fminf(mn, d);
                        if (offd) colMn[nf][e] = fminf(colMn[nf][e], d);
                    } else if (gi != gj) {
                        int idx = atomicAdd(&g_poscnt[gi], 1);
                        if (idx < MAXPOS) g_pos[gi * MAXPOS + idx] = d;
                        if (offd) {      // mirror pair (gj, gi)
                            int idx2 = atomicAdd(&g_poscnt[gj], 1);
                            if (idx2 < MAXPOS) g_pos[gj * MAXPOS + idx2] = d;
                        }
                    }
                }
            }
            atomicMin(&sMin[row], __float_as_uint(mn));
        }
    }
    if (offd) {
        #pragma unroll
        for (int nf = 0; nf < 4; ++nf)
            #pragma unroll
            for (int e = 0; e < 2; ++e) {
                int col = warpN * 32 + nf * 8 + 2 * thr + e;
                atomicMin(&sMinC[col], __float_as_uint(colMn[nf][e]));
            }
    }
    __syncthreads();
    if (tid < BM) {
        atomicMin(&g_hn[aBase + tid], sMin[tid]);
    } else if (offd) {
        atomicMin(&g_hn[jBase + tid - BM], sMinC[tid - BM]);
    }
}

// ---------------------------------------------------------------- reduction
__global__ void k_reduce(int B) {
    int i = blockIdx.x * blockDim.x + threadIdx.x;
    float s = 0.f; int c = 0;
    if (i < B) {
        float hn = __uint_as_float(g_hn[i]);
        int   n  = min(g_poscnt[i], MAXPOS);
        for (int e = 0; e < n; ++e) {
            float l = g_pos[i * MAXPOS + e] - hn + 1.0f;   // MARGIN = 1
            if (l > 0.f) { s += l; c++; }
        }
    }
    __shared__ float ss[256];
    __shared__ int   sc[256];
    int t = threadIdx.x;
    ss[t] = s; sc[t] = c;
    __syncthreads();
    for (int o = 128; o > 0; o >>= 1) {
        if (t < o) { ss[t] += ss[t + o]; sc[t] += sc[t + o]; }
        __syncthreads();
    }
    if (t == 0) {
        atomicAdd(&g_total, ss[0]);
        atomicAdd(&g_cnt,   sc[0]);
    }
}

__global__ void k_final(float* out) {
    int   c = g_cnt;
    out[0] = (c > 0) ? g_total / (float)c : 0.0f;
}

// ---------------------------------------------------------------- launch
extern "C" void kernel_launch(void* const* d_in, const int* in_sizes, int n_in,
                              void* d_out, int out_size) {
    const float* emb = (const float*)d_in[0];
    const void*  lab = d_in[1];
    float*       out = (float*)d_out;
    int B = in_sizes[1];   // 8192

    k_detect<<<1, 32>>>((const int*)lab);
    k_init<<<(B + 255) / 256, 256>>>(B);
    k_normalize<<<B, 64>>>(emb, lab, B);
    k_gemm<<<NTRI, 256>>>();
    k_reduce<<<(B + 255) / 256, 256>>>(B);
    k_final<<<1, 1>>>(out);
}